// round 15
// baseline (speedup 1.0000x reference)
#include <cuda_runtime.h>
#include <cuda_fp16.h>
#include <cstdint>
#include <math.h>

#define BATCH 4
#define SEQ   2048
#define DIM   1024

static constexpr size_t XSZ = (size_t)BATCH * SEQ * DIM;
static constexpr size_t WSZ = (size_t)DIM * DIM;
static constexpr size_t SD  = (size_t)SEQ * DIM;
static constexpr size_t SSZ = (size_t)SEQ * SEQ;

// ---- device-global scratch (allocation-free rules) ----
__device__ __half gX16[XSZ];                    // x -> fp16
__device__ __half gW16[3*WSZ];                  // Wq,Wk,Wv -> fp16
__device__ __half gQ16[XSZ];                    // Q fp16 (pre-scaled by 1/32)
__device__ __half gK16[XSZ];                    // K fp16
__device__ __half gVt16[XSZ];                   // V^T fp16: [b][d][s]
__device__ __half gP16[(size_t)BATCH * SSZ];    // P~ = exp(s), unnormalized fp16
__device__ float  gPart[(size_t)BATCH * 16 * 16 * 128];  // per-(b,itile,jtile) row sums

// ---- dependency flags (zeroed by reset kernel each call) ----
__device__ int convf;     // conv CTAs complete (count to 296)
__device__ int qf[64];    // Q proj strips complete (count to 8)
__device__ int kf[64];    // K proj strips complete (count to 8)
__device__ int sf[64];    // QK score rows complete (count to by+1)
__device__ int vf[512];   // V^T tiles complete (bool), [dtile*64 + s_strip]

// ============================ helpers ============================
__device__ __forceinline__ uint32_t smem_to_u32(const void* p) {
    uint32_t a;
    asm("{ .reg .u64 t; cvta.to.shared.u64 t, %1; cvt.u32.u64 %0, t; }" : "=r"(a) : "l"(p));
    return a;
}
__device__ __forceinline__ void cp16(uint32_t dst, const void* src) {
    asm volatile("cp.async.cg.shared.global [%0], [%1], 16;" :: "r"(dst), "l"(src));
}
#define CP_COMMIT() asm volatile("cp.async.commit_group;" ::: "memory")
#define CP_WAIT1()  asm volatile("cp.async.wait_group 1;" ::: "memory")

#define MMA(d, a, b) asm volatile( \
    "mma.sync.aligned.m16n8k16.row.col.f32.f16.f16.f32 " \
    "{%0,%1,%2,%3}, {%4,%5,%6,%7}, {%8,%9}, {%0,%1,%2,%3};" \
    : "+f"((d)[0]), "+f"((d)[1]), "+f"((d)[2]), "+f"((d)[3]) \
    : "r"((a)[0]), "r"((a)[1]), "r"((a)[2]), "r"((a)[3]), \
      "r"((b)[0]), "r"((b)[1]))

#define LDSM4(r0, r1, r2, r3, addr) asm volatile( \
    "ldmatrix.sync.aligned.m8n8.x4.shared.b16 {%0,%1,%2,%3}, [%4];" \
    : "=r"(r0), "=r"(r1), "=r"(r2), "=r"(r3) : "r"(addr))

__device__ __forceinline__ void store_single(__half* p, float v0, float v1) {
    *reinterpret_cast<__half2*>(p) = __halves2half2(__float2half(v0), __float2half(v1));
}

__device__ __forceinline__ void spin_ge(const int* f, int n) {
    while (*(volatile const int*)f < n) __nanosleep(64);
}

__device__ __forceinline__ __half2 cvt2(float2 v) {
    return __halves2half2(__float2half(v.x), __float2half(v.y));
}

// ===== smem: CTA tile 128(m) x 128(n), BK=64, rows 144B (128B data + 16B pad)
#define SA   0
#define SB   18432
#define STAGE_B  36864
#define NSTAGE   3
#define SMEM_TOTAL (NSTAGE * STAGE_B)   // 110592 -> 2 CTAs/SM

__device__ __forceinline__ void stage_copy(uint32_t st,
                                           const __half* __restrict__ a,
                                           const __half* __restrict__ b,
                                           int m0, int ldA, int n0, int ldB,
                                           int k0, int tid) {
#pragma unroll
    for (int i = 0; i < 4; i++) {
        const int u = tid + i * 256;
        const int row = u >> 3, c16 = u & 7;
        cp16(st + SA + row * 144 + c16 * 16,
             a + (size_t)(m0 + row) * ldA + k0 + c16 * 8);
    }
#pragma unroll
    for (int i = 0; i < 4; i++) {
        const int u = tid + i * 256;
        const int row = u >> 3, c16 = u & 7;
        cp16(st + SB + row * 144 + c16 * 16,
             b + (size_t)(n0 + row) * ldB + k0 + c16 * 8);
    }
}

// =================== uber kernel: conv + all 5 GEMM stages ===================
// bids: [0,296) conv (grid-stride)
//       [296,808) Qproj  [808,1320) Kproj  [1320,1832) Vtproj (spin convf)
//       [1832,2376) QK (spin qf/kf)        [2376,2888) PV (spin sf/vf)
__global__ __launch_bounds__(256, 2) void uber_kernel(
    float* __restrict__ out,
    const float* __restrict__ x,  const float* __restrict__ wq,
    const float* __restrict__ wk, const float* __restrict__ wv)
{
    extern __shared__ __align__(128) char smem[];
    const int tid = threadIdx.x;
    const int bid = blockIdx.x;

    if (bid < 296) {  // ---- fp32 -> fp16 converts, grid-stride, one wave ----
        const int NT = 296 * 256;
        const int XT = (int)(XSZ / 2);          // 4194304 float2 in x
        const int TOT = XT + (int)(3 * WSZ / 2);
        for (int i = bid * 256 + tid; i < TOT; i += NT) {
            if (i < XT) {
                ((__half2*)gX16)[i] = cvt2(((const float2*)x)[i]);
            } else {
                const int r = i - XT;
                const int w = r >> 19;          // WSZ/2 = 524288 = 2^19
                const int off = r & 524287;
                const float* s = (w == 0) ? wq : (w == 1) ? wk : wv;
                ((__half2*)(gW16 + (size_t)w * WSZ))[off] = cvt2(((const float2*)s)[off]);
            }
        }
        __syncthreads();
        if (tid == 0) { __threadfence(); atomicAdd(&convf, 1); }
        return;
    }

    const int wid = tid >> 5, lane = tid & 31;
    const int g = lane >> 2, t = lane & 3;
    const int wm = (wid & 1) * 64, wn = (wid >> 1) * 32;   // 8 warps: 2(m) x 4(n)

    const __half *pA, *pB;
    int m0, n0, ldA, ldB, nch, bb = 0, mode;
    if (bid < 1320) {        // Q or K projection: A = x16, B = Wq/Wk
        mode = (bid < 808) ? 0 : 1;
        const int bx = (bid - 296) & 511;
        m0 = (bx >> 3) * 128; n0 = (bx & 7) * 128;
        pA = gX16; ldA = DIM;
        pB = gW16 + (size_t)mode * WSZ; ldB = DIM;
        nch = DIM / 64;
        if (tid == 0) { spin_ge(&convf, 296); __threadfence(); }
        __syncthreads();
    } else if (bid < 1832) { // V^T: A = Wv16 (d), B = x16 (s-global)
        mode = 2;
        const int v = bid - 1320;
        m0 = (v >> 6) * 128; n0 = (v & 63) * 128;
        pA = gW16 + 2 * WSZ; ldA = DIM;
        pB = gX16; ldB = DIM;
        nch = DIM / 64;
        if (tid == 0) { spin_ge(&convf, 296); __threadfence(); }
        __syncthreads();
    } else if (bid < 2376) { // QK scores, heavy-first triangular
        mode = 3;
        const int idx = bid - 1832;
        bb = idx & 3;
        const int r = idx >> 2;
        int by = 0, bxt = 0, acc_ = 0;
#pragma unroll
        for (int byy = 15; byy >= 0; byy--) {
            const int cnt = byy + 1;
            if (r >= acc_ && r < acc_ + cnt) { by = byy; bxt = r - acc_; }
            acc_ += cnt;
        }
        m0 = by * 128; n0 = bxt * 128;
        pA = gQ16 + (size_t)bb * SD; ldA = DIM;
        pB = gK16 + (size_t)bb * SD; ldB = DIM;
        nch = DIM / 64;
        if (tid == 0) {      // wait for Q strip (bb,by) and K strip (bb,bxt)
            spin_ge(&qf[bb * 16 + by], 8);
            spin_ge(&kf[bb * 16 + bxt], 8);
            __threadfence();
        }
        __syncthreads();
    } else {                 // PV, heavy i-tiles first
        mode = 4;
        const int idx = bid - 2376;
        const int by = 15 - (idx >> 5);
        const int inner = idx & 31;
        bb = inner & 3;
        const int dx = inner >> 2;
        m0 = by * 128; n0 = dx * 128;
        pA = gP16 + (size_t)bb * SSZ; ldA = SEQ;
        pB = gVt16 + (size_t)bb * SD; ldB = SEQ;
        nch = 2 * (by + 1);
        if (tid == 0) {      // wait for score row by and V^T tiles (dx, 0..by)
            spin_ge(&sf[bb * 16 + by], by + 1);
            for (int jt = 0; jt <= by; jt++)
                spin_ge(&vf[dx * 64 + bb * 16 + jt], 1);
            __threadfence();
        }
        __syncthreads();
    }

    const uint32_t sb = smem_to_u32(smem);
    const uint32_t aoff = (uint32_t)(wm + (lane & 15)) * 144 + (uint32_t)(lane >> 4) * 16;
    const uint32_t boff = (uint32_t)(wn + ((lane >> 1) & 8) + (lane & 7)) * 144
                        + (uint32_t)(lane & 8) * 2;

#pragma unroll
    for (int s = 0; s < 2; s++) {
        if (s < nch) stage_copy(sb + s * STAGE_B, pA, pB, m0, ldA, n0, ldB, s * 64, tid);
        CP_COMMIT();
    }

    float acc[4][4][4];
#pragma unroll
    for (int i = 0; i < 4; i++)
#pragma unroll
        for (int j = 0; j < 4; j++)
#pragma unroll
            for (int k = 0; k < 4; k++) acc[i][j][k] = 0.0f;

    for (int c = 0; c < nch; c++) {
        CP_WAIT1();
        __syncthreads();
        const uint32_t st = sb + (uint32_t)(c % NSTAGE) * STAGE_B;
#pragma unroll
        for (int kk = 0; kk < 4; kk++) {
            const uint32_t ka = st + kk * 32;
            uint32_t bfr[4][2];
            LDSM4(bfr[0][0], bfr[0][1], bfr[1][0], bfr[1][1], ka + SB + boff);
            LDSM4(bfr[2][0], bfr[2][1], bfr[3][0], bfr[3][1], ka + SB + boff + 2304);
#pragma unroll
            for (int mt = 0; mt < 4; mt++) {
                uint32_t av[4];
                LDSM4(av[0], av[1], av[2], av[3], ka + SA + aoff + mt * 2304);
#pragma unroll
                for (int nt = 0; nt < 4; nt++) MMA(acc[mt][nt], av, bfr[nt]);
            }
        }
        const int cn = c + 2;
        if (cn < nch)
            stage_copy(sb + (uint32_t)(cn % NSTAGE) * STAGE_B,
                       pA, pB, m0, ldA, n0, ldB, cn * 64, tid);
        CP_COMMIT();
    }

    // ---------------- epilogues ----------------
    if (mode == 3) {
        // fused exp: P~ = exp(min(s,10)) (0 above diagonal) + per-row partial sums
        __half* P = gP16 + (size_t)bb * SSZ;
        float* rowsum = (float*)smem;
        __syncthreads();
        if (tid < 128) rowsum[tid] = 0.0f;
        __syncthreads();
#pragma unroll
        for (int mt = 0; mt < 4; mt++) {
            const int r = m0 + wm + mt * 16 + g;
            float s0 = 0.0f, s1 = 0.0f;
#pragma unroll
            for (int nt = 0; nt < 4; nt++) {
                const float* a = acc[mt][nt];
                const int cc = n0 + wn + nt * 8 + 2 * t;
                const float e0 = (cc     <= r) ? __expf(fminf(a[0], 10.0f)) : 0.0f;
                const float e1 = (cc + 1 <= r) ? __expf(fminf(a[1], 10.0f)) : 0.0f;
                const float e2 = (cc     <= r + 8) ? __expf(fminf(a[2], 10.0f)) : 0.0f;
                const float e3 = (cc + 1 <= r + 8) ? __expf(fminf(a[3], 10.0f)) : 0.0f;
                store_single(P + (size_t)r * SEQ + cc, e0, e1);
                store_single(P + (size_t)(r + 8) * SEQ + cc, e2, e3);
                s0 += e0 + e1;
                s1 += e2 + e3;
            }
            s0 += __shfl_xor_sync(~0u, s0, 1); s0 += __shfl_xor_sync(~0u, s0, 2);
            s1 += __shfl_xor_sync(~0u, s1, 1); s1 += __shfl_xor_sync(~0u, s1, 2);
            if (t == 0) {
                atomicAdd(&rowsum[wm + mt * 16 + g], s0);
                atomicAdd(&rowsum[wm + mt * 16 + g + 8], s1);
            }
        }
        __syncthreads();
        if (tid < 128)
            gPart[(((size_t)bb * 16 + (m0 >> 7)) * 16 + (n0 >> 7)) * 128 + tid] = rowsum[tid];
        __syncthreads();
        if (tid == 0) { __threadfence(); atomicAdd(&sf[bb * 16 + (m0 >> 7)], 1); }
        return;
    }

    float* invb = (float*)smem;
    if (mode == 4) {
        // inline row-sum inversion (jt ascending: deterministic)
        const int by = m0 >> 7;
        __syncthreads();
        if (tid < 128) {
            float s = 0.0f;
            const size_t basep = (((size_t)bb * 16 + by) * 16) * 128 + tid;
            for (int jt = 0; jt <= by; jt++)
                s += gPart[basep + (size_t)jt * 128];
            invb[tid] = 1.0f / s;
        }
        __syncthreads();
    }

#pragma unroll
    for (int mt = 0; mt < 4; mt++) {
        const int r = m0 + wm + mt * 16 + g;
        float i0 = 1.0f, i1 = 1.0f;
        if (mode == 4) {
            i0 = invb[wm + mt * 16 + g];
            i1 = invb[wm + mt * 16 + g + 8];
        }
#pragma unroll
        for (int nt = 0; nt < 4; nt++) {
            const float* a = acc[mt][nt];
            const int cc = n0 + wn + nt * 8 + 2 * t;
            if (mode == 0) {         // Q pre-scaled by 1/32 (exact power of 2)
                store_single(gQ16 + (size_t)r * DIM + cc,
                             a[0] * 0.03125f, a[1] * 0.03125f);
                store_single(gQ16 + (size_t)(r + 8) * DIM + cc,
                             a[2] * 0.03125f, a[3] * 0.03125f);
            } else if (mode == 1) {
                store_single(gK16 + (size_t)r * DIM + cc, a[0], a[1]);
                store_single(gK16 + (size_t)(r + 8) * DIM + cc, a[2], a[3]);
            } else if (mode == 2) {  // V^T store
                const int b = cc >> 11, s = cc & (SEQ - 1);
                const size_t base = (size_t)b * SD;
                store_single(gVt16 + base + (size_t)r * SEQ + s, a[0], a[1]);
                store_single(gVt16 + base + (size_t)(r + 8) * SEQ + s, a[2], a[3]);
            } else {                 // mode 4: O = (P~ . V) * inv_rowsum
                float* O = out + (size_t)bb * SD;
                float2 v0, v1;
                v0.x = a[0] * i0; v0.y = a[1] * i0;
                v1.x = a[2] * i1; v1.y = a[3] * i1;
                *(float2*)(O + (size_t)r * DIM + cc)       = v0;
                *(float2*)(O + (size_t)(r + 8) * DIM + cc) = v1;
            }
        }
    }

    // producer completion flags (tid0-only gpu fence; bar.sync gives cumulativity)
    if (mode <= 2) {
        __syncthreads();
        if (tid == 0) {
            __threadfence();
            if (mode == 0)      atomicAdd(&qf[(bid - 296) >> 3], 1);
            else if (mode == 1) atomicAdd(&kf[(bid - 808) >> 3], 1);
            else {
                const int v = bid - 1320;
                atomicAdd(&vf[(v >> 6) * 64 + (v & 63)], 1);
            }
        }
    }
}

// ================= flag reset (flags persist across graph replays) =================
__global__ __launch_bounds__(256) void reset_kernel()
{
    const int i = threadIdx.x;
    if (i == 0) convf = 0;
    if (i < 64)  { qf[i] = 0; kf[i] = 0; sf[i] = 0; }
    if (i < 256) { vf[i] = 0; vf[i + 256] = 0; }
}

// ---------------------------------------------------------------------------
extern "C" void kernel_launch(void* const* d_in, const int* in_sizes, int n_in,
                              void* d_out, int out_size)
{
    (void)in_sizes; (void)n_in; (void)out_size;
    const float* x  = (const float*)d_in[0];
    const float* wq = (const float*)d_in[1];
    const float* wk = (const float*)d_in[2];
    const float* wv = (const float*)d_in[3];
    float* out = (float*)d_out;

    cudaFuncSetAttribute(uber_kernel, cudaFuncAttributeMaxDynamicSharedMemorySize, SMEM_TOTAL);

    reset_kernel<<<1, 256>>>();
    uber_kernel<<<2888, 256, SMEM_TOTAL>>>(out, x, wq, wk, wv);
}

// round 16
// speedup vs baseline: 1.0998x; 1.0998x over previous
#include <cuda_runtime.h>
#include <cuda_fp16.h>
#include <cstdint>
#include <math.h>

#define BATCH 4
#define SEQ   2048
#define DIM   1024

static constexpr size_t XSZ = (size_t)BATCH * SEQ * DIM;
static constexpr size_t WSZ = (size_t)DIM * DIM;
static constexpr size_t SD  = (size_t)SEQ * DIM;
static constexpr size_t SSZ = (size_t)SEQ * SEQ;

// ---- device-global scratch (allocation-free rules) ----
__device__ __half gX16[XSZ];                    // x -> fp16
__device__ __half gW16[3*WSZ];                  // Wq,Wk,Wv -> fp16
__device__ __half gQ16[XSZ];                    // Q fp16 (pre-scaled by 1/32)
__device__ __half gK16[XSZ];                    // K fp16
__device__ __half gVt16[XSZ];                   // V^T fp16: [b][d][s]
__device__ __half gP16[(size_t)BATCH * SSZ];    // P~ = exp(s), unnormalized fp16
__device__ float  gPart[(size_t)BATCH * 16 * 16 * 128];  // per-(b,itile,jtile) row sums
__device__ int    sf[64];                       // QK score-row completion counters

// ============================ helpers ============================
__device__ __forceinline__ uint32_t smem_to_u32(const void* p) {
    uint32_t a;
    asm("{ .reg .u64 t; cvta.to.shared.u64 t, %1; cvt.u32.u64 %0, t; }" : "=r"(a) : "l"(p));
    return a;
}
__device__ __forceinline__ void cp16(uint32_t dst, const void* src) {
    asm volatile("cp.async.cg.shared.global [%0], [%1], 16;" :: "r"(dst), "l"(src));
}
#define CP_COMMIT() asm volatile("cp.async.commit_group;" ::: "memory")
#define CP_WAIT1()  asm volatile("cp.async.wait_group 1;" ::: "memory")

#define MMA(d, a, b) asm volatile( \
    "mma.sync.aligned.m16n8k16.row.col.f32.f16.f16.f32 " \
    "{%0,%1,%2,%3}, {%4,%5,%6,%7}, {%8,%9}, {%0,%1,%2,%3};" \
    : "+f"((d)[0]), "+f"((d)[1]), "+f"((d)[2]), "+f"((d)[3]) \
    : "r"((a)[0]), "r"((a)[1]), "r"((a)[2]), "r"((a)[3]), \
      "r"((b)[0]), "r"((b)[1]))

#define LDSM4(r0, r1, r2, r3, addr) asm volatile( \
    "ldmatrix.sync.aligned.m8n8.x4.shared.b16 {%0,%1,%2,%3}, [%4];" \
    : "=r"(r0), "=r"(r1), "=r"(r2), "=r"(r3) : "r"(addr))

__device__ __forceinline__ void store_single(__half* p, float v0, float v1) {
    *reinterpret_cast<__half2*>(p) = __halves2half2(__float2half(v0), __float2half(v1));
}

__device__ __forceinline__ void spin_ge(const int* f, int n) {
    while (*(volatile const int*)f < n) __nanosleep(64);
}

// ===== smem: CTA tile 128(m) x 128(n), BK=64, rows 144B (128B data + 16B pad)
#define SA   0
#define SB   18432
#define STAGE_B  36864
#define NSTAGE   3
#define SMEM_TOTAL (NSTAGE * STAGE_B)   // 110592 -> 2 CTAs/SM

__device__ __forceinline__ void stage_copy(uint32_t st,
                                           const __half* __restrict__ a,
                                           const __half* __restrict__ b,
                                           int m0, int ldA, int n0, int ldB,
                                           int k0, int tid) {
#pragma unroll
    for (int i = 0; i < 4; i++) {
        const int u = tid + i * 256;
        const int row = u >> 3, c16 = u & 7;
        cp16(st + SA + row * 144 + c16 * 16,
             a + (size_t)(m0 + row) * ldA + k0 + c16 * 8);
    }
#pragma unroll
    for (int i = 0; i < 4; i++) {
        const int u = tid + i * 256;
        const int row = u >> 3, c16 = u & 7;
        cp16(st + SB + row * 144 + c16 * 16,
             b + (size_t)(n0 + row) * ldB + k0 + c16 * 8);
    }
}

// ================== shared mainloop (identical FP semantics to R13) ==================
__device__ __forceinline__ void gemm_mainloop(
    char* smem, uint32_t sb, const __half* pA, const __half* pB,
    int m0, int ldA, int n0, int ldB, int nch,
    int tid, uint32_t aoff, uint32_t boff, float acc[4][4][4])
{
#pragma unroll
    for (int s = 0; s < 2; s++) {
        if (s < nch) stage_copy(sb + s * STAGE_B, pA, pB, m0, ldA, n0, ldB, s * 64, tid);
        CP_COMMIT();
    }
    for (int c = 0; c < nch; c++) {
        CP_WAIT1();
        __syncthreads();
        const uint32_t st = sb + (uint32_t)(c % NSTAGE) * STAGE_B;
#pragma unroll
        for (int kk = 0; kk < 4; kk++) {
            const uint32_t ka = st + kk * 32;
            uint32_t bfr[4][2];
            LDSM4(bfr[0][0], bfr[0][1], bfr[1][0], bfr[1][1], ka + SB + boff);
            LDSM4(bfr[2][0], bfr[2][1], bfr[3][0], bfr[3][1], ka + SB + boff + 2304);
#pragma unroll
            for (int mt = 0; mt < 4; mt++) {
                uint32_t av[4];
                LDSM4(av[0], av[1], av[2], av[3], ka + SA + aoff + mt * 2304);
#pragma unroll
                for (int nt = 0; nt < 4; nt++) MMA(acc[mt][nt], av, bfr[nt]);
            }
        }
        const int cn = c + 2;
        if (cn < nch)
            stage_copy(sb + (uint32_t)(cn % NSTAGE) * STAGE_B,
                       pA, pB, m0, ldA, n0, ldB, cn * 64, tid);
        CP_COMMIT();
    }
}

// =================== launch 2: Q, K, V^T projections ===================
// bids: [0,512) Q  [512,1024) K  [1024,1536) V^T
__global__ __launch_bounds__(256, 2) void proj_kernel()
{
    extern __shared__ __align__(128) char smem[];
    const int tid = threadIdx.x, wid = tid >> 5, lane = tid & 31;
    const int g = lane >> 2, t = lane & 3;
    const int wm = (wid & 1) * 64, wn = (wid >> 1) * 32;
    const int bid = blockIdx.x;

    const __half *pA, *pB;
    int m0, n0, mode;
    if (bid < 1024) {        // Q or K: A = x16, B = Wq/Wk
        mode = (bid < 512) ? 0 : 1;
        const int bx = bid & 511;
        m0 = (bx >> 3) * 128; n0 = (bx & 7) * 128;
        pA = gX16; pB = gW16 + (size_t)mode * WSZ;
    } else {                 // V^T: A = Wv16 (d), B = x16 (s-global)
        mode = 2;
        const int v = bid - 1024;
        m0 = (v >> 6) * 128; n0 = (v & 63) * 128;
        pA = gW16 + 2 * WSZ; pB = gX16;
    }

    const uint32_t sb = smem_to_u32(smem);
    const uint32_t aoff = (uint32_t)(wm + (lane & 15)) * 144 + (uint32_t)(lane >> 4) * 16;
    const uint32_t boff = (uint32_t)(wn + ((lane >> 1) & 8) + (lane & 7)) * 144
                        + (uint32_t)(lane & 8) * 2;

    float acc[4][4][4];
#pragma unroll
    for (int i = 0; i < 4; i++)
#pragma unroll
        for (int j = 0; j < 4; j++)
#pragma unroll
            for (int k = 0; k < 4; k++) acc[i][j][k] = 0.0f;

    gemm_mainloop(smem, sb, pA, pB, m0, DIM, n0, DIM, DIM / 64,
                  tid, aoff, boff, acc);

#pragma unroll
    for (int mt = 0; mt < 4; mt++) {
        const int r = m0 + wm + mt * 16 + g;
#pragma unroll
        for (int nt = 0; nt < 4; nt++) {
            const float* a = acc[mt][nt];
            const int cc = n0 + wn + nt * 8 + 2 * t;
            if (mode == 0) {         // Q pre-scaled by 1/32 (exact power of 2)
                store_single(gQ16 + (size_t)r * DIM + cc,
                             a[0] * 0.03125f, a[1] * 0.03125f);
                store_single(gQ16 + (size_t)(r + 8) * DIM + cc,
                             a[2] * 0.03125f, a[3] * 0.03125f);
            } else if (mode == 1) {
                store_single(gK16 + (size_t)r * DIM + cc, a[0], a[1]);
                store_single(gK16 + (size_t)(r + 8) * DIM + cc, a[2], a[3]);
            } else {                 // V^T store
                const int b = cc >> 11, s = cc & (SEQ - 1);
                const size_t base = (size_t)b * SD;
                store_single(gVt16 + base + (size_t)r * SEQ + s, a[0], a[1]);
                store_single(gVt16 + base + (size_t)(r + 8) * SEQ + s, a[2], a[3]);
            }
        }
    }
}

// =================== launch 3: fused QK scores -> PV ===================
// bids: [0,544) QK heavy-first (exp epilogue, sf release)
//       [544,1056) PV heavy-first (sf acquire, inline inv)
__global__ __launch_bounds__(256, 2) void qkpv_kernel(float* __restrict__ out)
{
    extern __shared__ __align__(128) char smem[];
    const int tid = threadIdx.x, wid = tid >> 5, lane = tid & 31;
    const int g = lane >> 2, t = lane & 3;
    const int wm = (wid & 1) * 64, wn = (wid >> 1) * 32;
    const int bid = blockIdx.x;

    const __half *pA, *pB;
    int m0, n0, ldA, ldB, nch, bb;
    const bool isQK = (bid < 544);
    if (isQK) {              // QK scores, heavy-first triangular
        bb = bid & 3;
        const int r = bid >> 2;
        int by = 0, bxt = 0, acc_ = 0;
#pragma unroll
        for (int byy = 15; byy >= 0; byy--) {
            const int cnt = byy + 1;
            if (r >= acc_ && r < acc_ + cnt) { by = byy; bxt = r - acc_; }
            acc_ += cnt;
        }
        m0 = by * 128; n0 = bxt * 128;
        pA = gQ16 + (size_t)bb * SD; ldA = DIM;
        pB = gK16 + (size_t)bb * SD; ldB = DIM;
        nch = DIM / 64;
    } else {                 // PV, heavy i-tiles first
        const int idx = bid - 544;
        const int by = 15 - (idx >> 5);
        const int inner = idx & 31;
        bb = inner & 3;
        const int dx = inner >> 2;
        m0 = by * 128; n0 = dx * 128;
        pA = gP16 + (size_t)bb * SSZ; ldA = SEQ;
        pB = gVt16 + (size_t)bb * SD; ldB = SEQ;
        nch = 2 * (by + 1);
        if (tid == 0) {      // all QK tiles of score row `by` must be complete
            spin_ge(&sf[bb * 16 + by], by + 1);
            __threadfence();
        }
        __syncthreads();
    }

    const uint32_t sb = smem_to_u32(smem);
    const uint32_t aoff = (uint32_t)(wm + (lane & 15)) * 144 + (uint32_t)(lane >> 4) * 16;
    const uint32_t boff = (uint32_t)(wn + ((lane >> 1) & 8) + (lane & 7)) * 144
                        + (uint32_t)(lane & 8) * 2;

    float acc[4][4][4];
#pragma unroll
    for (int i = 0; i < 4; i++)
#pragma unroll
        for (int j = 0; j < 4; j++)
#pragma unroll
            for (int k = 0; k < 4; k++) acc[i][j][k] = 0.0f;

    gemm_mainloop(smem, sb, pA, pB, m0, ldA, n0, ldB, nch, tid, aoff, boff, acc);

    if (isQK) {
        // fused exp: P~ = exp(min(s,10)) (0 above diagonal) + per-row partial sums
        __half* P = gP16 + (size_t)bb * SSZ;
        float* rowsum = (float*)smem;
        __syncthreads();
        if (tid < 128) rowsum[tid] = 0.0f;
        __syncthreads();
#pragma unroll
        for (int mt = 0; mt < 4; mt++) {
            const int r = m0 + wm + mt * 16 + g;
            float s0 = 0.0f, s1 = 0.0f;
#pragma unroll
            for (int nt = 0; nt < 4; nt++) {
                const float* a = acc[mt][nt];
                const int cc = n0 + wn + nt * 8 + 2 * t;
                const float e0 = (cc     <= r) ? __expf(fminf(a[0], 10.0f)) : 0.0f;
                const float e1 = (cc + 1 <= r) ? __expf(fminf(a[1], 10.0f)) : 0.0f;
                const float e2 = (cc     <= r + 8) ? __expf(fminf(a[2], 10.0f)) : 0.0f;
                const float e3 = (cc + 1 <= r + 8) ? __expf(fminf(a[3], 10.0f)) : 0.0f;
                store_single(P + (size_t)r * SEQ + cc, e0, e1);
                store_single(P + (size_t)(r + 8) * SEQ + cc, e2, e3);
                s0 += e0 + e1;
                s1 += e2 + e3;
            }
            s0 += __shfl_xor_sync(~0u, s0, 1); s0 += __shfl_xor_sync(~0u, s0, 2);
            s1 += __shfl_xor_sync(~0u, s1, 1); s1 += __shfl_xor_sync(~0u, s1, 2);
            if (t == 0) {
                atomicAdd(&rowsum[wm + mt * 16 + g], s0);
                atomicAdd(&rowsum[wm + mt * 16 + g + 8], s1);
            }
        }
        __syncthreads();
        if (tid < 128)
            gPart[(((size_t)bb * 16 + (m0 >> 7)) * 16 + (n0 >> 7)) * 128 + tid] = rowsum[tid];
        __syncthreads();
        if (tid == 0) { __threadfence(); atomicAdd(&sf[bb * 16 + (m0 >> 7)], 1); }
        return;
    }

    // PV epilogue: inline row-sum inversion (jt ascending: deterministic)
    float* invb = (float*)smem;
    {
        const int by = m0 >> 7;
        __syncthreads();
        if (tid < 128) {
            float s = 0.0f;
            const size_t basep = (((size_t)bb * 16 + by) * 16) * 128 + tid;
            for (int jt = 0; jt <= by; jt++)
                s += gPart[basep + (size_t)jt * 128];
            invb[tid] = 1.0f / s;
        }
        __syncthreads();
    }

#pragma unroll
    for (int mt = 0; mt < 4; mt++) {
        const int r = m0 + wm + mt * 16 + g;
        const float i0 = invb[wm + mt * 16 + g];
        const float i1 = invb[wm + mt * 16 + g + 8];
#pragma unroll
        for (int nt = 0; nt < 4; nt++) {
            const float* a = acc[mt][nt];
            const int cc = n0 + wn + nt * 8 + 2 * t;
            float* O = out + (size_t)bb * SD;
            float2 v0, v1;
            v0.x = a[0] * i0; v0.y = a[1] * i0;
            v1.x = a[2] * i1; v1.y = a[3] * i1;
            *(float2*)(O + (size_t)r * DIM + cc)       = v0;
            *(float2*)(O + (size_t)(r + 8) * DIM + cc) = v1;
        }
    }
}

// ======== launch 1: fp32 -> fp16 convert (x + all W) + sf zeroing ========
__global__ __launch_bounds__(256) void conv_kernel(const float* __restrict__ x,
                                                   const float* __restrict__ wq,
                                                   const float* __restrict__ wk,
                                                   const float* __restrict__ wv)
{
    const int b = blockIdx.x;
    if (b == 22528) {                    // zero sf flags (persist across replays)
        if (threadIdx.x < 64) sf[threadIdx.x] = 0;
        return;
    }
    const float* s; __half* d; int i;
    if (b < 16384) {                     // x
        s = x; d = gX16; i = b * 256 + threadIdx.x;
    } else {                             // W
        const int w = (b - 16384) >> 11, b2 = (b - 16384) & 2047;
        s = (w == 0) ? wq : (w == 1) ? wk : wv;
        d = gW16 + (size_t)w * WSZ;
        i = b2 * 256 + threadIdx.x;
    }
    float2 v = ((const float2*)s)[i];
    ((__half2*)d)[i] = __halves2half2(__float2half(v.x), __float2half(v.y));
}

// ---------------------------------------------------------------------------
extern "C" void kernel_launch(void* const* d_in, const int* in_sizes, int n_in,
                              void* d_out, int out_size)
{
    (void)in_sizes; (void)n_in; (void)out_size;
    const float* x  = (const float*)d_in[0];
    const float* wq = (const float*)d_in[1];
    const float* wk = (const float*)d_in[2];
    const float* wv = (const float*)d_in[3];
    float* out = (float*)d_out;

    cudaFuncSetAttribute(proj_kernel, cudaFuncAttributeMaxDynamicSharedMemorySize, SMEM_TOTAL);
    cudaFuncSetAttribute(qkpv_kernel, cudaFuncAttributeMaxDynamicSharedMemorySize, SMEM_TOTAL);

    // converts + sf zeroing
    conv_kernel<<<16384 + 3 * 2048 + 1, 256>>>(x, wq, wk, wv);
    // Q (pre-scaled), K, V^T projections
    proj_kernel<<<1536, 256, SMEM_TOTAL>>>();
    // fused: causal scores + exp + partial sums -> PV with device-side row flags
    qkpv_kernel<<<1056, 256, SMEM_TOTAL>>>(out);
}

// round 17
// speedup vs baseline: 1.1562x; 1.0513x over previous
#include <cuda_runtime.h>
#include <cuda_fp16.h>
#include <cstdint>
#include <math.h>

#define BATCH 4
#define SEQ   2048
#define DIM   1024

static constexpr size_t XSZ = (size_t)BATCH * SEQ * DIM;
static constexpr size_t WSZ = (size_t)DIM * DIM;
static constexpr size_t SD  = (size_t)SEQ * DIM;
static constexpr size_t SSZ = (size_t)SEQ * SEQ;

// ---- device-global scratch (allocation-free rules) ----
__device__ __half gX16[XSZ];                    // x -> fp16
__device__ __half gW16[3*WSZ];                  // Wq,Wk,Wv -> fp16
__device__ __half gQ16[XSZ];                    // Q fp16 (pre-scaled by 1/32)
__device__ __half gK16[XSZ];                    // K fp16
__device__ __half gVt16[XSZ];                   // V^T fp16: [b][d][s]
__device__ __half gP16[(size_t)BATCH * SSZ];    // P~ = exp(s), unnormalized fp16
__device__ float  gPart[(size_t)BATCH * 16 * 16 * 128];  // per-(b,itile,jtile) row sums

// ============================ helpers ============================
__device__ __forceinline__ uint32_t smem_to_u32(const void* p) {
    uint32_t a;
    asm("{ .reg .u64 t; cvta.to.shared.u64 t, %1; cvt.u32.u64 %0, t; }" : "=r"(a) : "l"(p));
    return a;
}
__device__ __forceinline__ void cp16(uint32_t dst, const void* src) {
    asm volatile("cp.async.cg.shared.global [%0], [%1], 16;" :: "r"(dst), "l"(src));
}
#define CP_COMMIT() asm volatile("cp.async.commit_group;" ::: "memory")
#define CP_WAIT1()  asm volatile("cp.async.wait_group 1;" ::: "memory")

#define MMA(d, a, b) asm volatile( \
    "mma.sync.aligned.m16n8k16.row.col.f32.f16.f16.f32 " \
    "{%0,%1,%2,%3}, {%4,%5,%6,%7}, {%8,%9}, {%0,%1,%2,%3};" \
    : "+f"((d)[0]), "+f"((d)[1]), "+f"((d)[2]), "+f"((d)[3]) \
    : "r"((a)[0]), "r"((a)[1]), "r"((a)[2]), "r"((a)[3]), \
      "r"((b)[0]), "r"((b)[1]))

#define LDSM4(r0, r1, r2, r3, addr) asm volatile( \
    "ldmatrix.sync.aligned.m8n8.x4.shared.b16 {%0,%1,%2,%3}, [%4];" \
    : "=r"(r0), "=r"(r1), "=r"(r2), "=r"(r3) : "r"(addr))

__device__ __forceinline__ void store_single(__half* p, float v0, float v1) {
    *reinterpret_cast<__half2*>(p) = __halves2half2(__float2half(v0), __float2half(v1));
}

// ===== smem: CTA tile 128(m) x 128(n), BK=64, rows 144B (128B data + 16B pad)
#define SA   0
#define SB   18432
#define STAGE_B  36864
#define NSTAGE   3
#define SMEM_TOTAL (NSTAGE * STAGE_B)   // 110592 -> 2 CTAs/SM

__device__ __forceinline__ void stage_copy(uint32_t st,
                                           const __half* __restrict__ a,
                                           const __half* __restrict__ b,
                                           int m0, int ldA, int n0, int ldB,
                                           int k0, int tid) {
#pragma unroll
    for (int i = 0; i < 4; i++) {
        const int u = tid + i * 256;
        const int row = u >> 3, c16 = u & 7;
        cp16(st + SA + row * 144 + c16 * 16,
             a + (size_t)(m0 + row) * ldA + k0 + c16 * 8);
    }
#pragma unroll
    for (int i = 0; i < 4; i++) {
        const int u = tid + i * 256;
        const int row = u >> 3, c16 = u & 7;
        cp16(st + SB + row * 144 + c16 * 16,
             b + (size_t)(n0 + row) * ldB + k0 + c16 * 8);
    }
}

// =================== single-pass fp16 HMMA GEMM ===================
// D[128(m) x 128(n)] = A(128xK) . B(128xK)^T
// MODE 0: Q/K projections (bz selects)    MODE 3: fused QK-scores + V^T proj
// MODE 2: O = (P~ . V) * inv (inline row-sum inversion)
template <int MODE>
__global__ __launch_bounds__(256, 2) void mma_kernel(float* __restrict__ out)
{
    extern __shared__ __align__(128) char smem[];
    const int tid = threadIdx.x, wid = tid >> 5, lane = tid & 31;
    const int g = lane >> 2, t = lane & 3;
    const int wm = (wid & 1) * 64, wn = (wid >> 1) * 32;   // 8 warps: 2(m) x 4(n)

    const __half *pA, *pB;
    int m0, n0, ldA, ldB, nch, bb = 0;
    bool isQK = false;
    if (MODE == 0) {         // Q or K projection: A = x16, B = Wq/Wk
        const int bx = blockIdx.x;
        m0 = (bx >> 3) * 128; n0 = (bx & 7) * 128;
        pA = gX16; ldA = DIM;
        pB = gW16 + (size_t)blockIdx.z * WSZ; ldB = DIM;
        nch = DIM / 64;
    } else if (MODE == 3) {  // fused: QK scores (idx<544, heavy-first) else V^T proj
        const int idx = blockIdx.x;
        if (idx < 544) {
            isQK = true;
            bb = idx & 3;                       // interleave batches
            const int r = idx >> 2;             // triangular rank, heavy-first
            int by = 0, bxt = 0, acc_ = 0;
#pragma unroll
            for (int byy = 15; byy >= 0; byy--) {
                const int cnt = byy + 1;
                if (r >= acc_ && r < acc_ + cnt) { by = byy; bxt = r - acc_; }
                acc_ += cnt;
            }
            m0 = by * 128; n0 = bxt * 128;
            pA = gQ16 + (size_t)bb * SD; ldA = DIM;
            pB = gK16 + (size_t)bb * SD; ldB = DIM;
        } else {             // V^T: A = Wv16 (d), B = x16 (s-global)
            const int v = idx - 544;
            m0 = (v >> 6) * 128; n0 = (v & 63) * 128;
            pA = gW16 + 2 * WSZ; ldA = DIM;
            pB = gX16; ldB = DIM;
        }
        nch = DIM / 64;
    } else {                 // PV: A = P~16 (i), B = V^T16 (d), k = j; heavy-first
        bb = blockIdx.x >> 3;
        const int bx = blockIdx.x & 7;                 // d-tile
        const int by = 15 - blockIdx.y;                // i-tile
        m0 = by * 128; n0 = bx * 128;
        pA = gP16 + (size_t)bb * SSZ; ldA = SEQ;
        pB = gVt16 + (size_t)bb * SD; ldB = SEQ;
        nch = 2 * (by + 1);  // causal: j < (by+1)*128
    }

    const uint32_t sb = smem_to_u32(smem);

    // ldmatrix lane offsets (k-invariant); row stride 144 B
    const uint32_t aoff = (uint32_t)(wm + (lane & 15)) * 144 + (uint32_t)(lane >> 4) * 16;
    const uint32_t boff = (uint32_t)(wn + ((lane >> 1) & 8) + (lane & 7)) * 144
                        + (uint32_t)(lane & 8) * 2;

    // prologue: 2 stages in flight (nch >= 2 in all modes)
#pragma unroll
    for (int s = 0; s < 2; s++) {
        if (s < nch) stage_copy(sb + s * STAGE_B, pA, pB, m0, ldA, n0, ldB, s * 64, tid);
        CP_COMMIT();
    }

    float acc[4][4][4];
#pragma unroll
    for (int i = 0; i < 4; i++)
#pragma unroll
        for (int j = 0; j < 4; j++)
#pragma unroll
            for (int k = 0; k < 4; k++) acc[i][j][k] = 0.0f;

    for (int c = 0; c < nch; c++) {
        CP_WAIT1();
        __syncthreads();
        const uint32_t st = sb + (uint32_t)(c % NSTAGE) * STAGE_B;
#pragma unroll
        for (int kk = 0; kk < 4; kk++) {
            const uint32_t ka = st + kk * 32;
            uint32_t bfr[4][2];
            LDSM4(bfr[0][0], bfr[0][1], bfr[1][0], bfr[1][1], ka + SB + boff);
            LDSM4(bfr[2][0], bfr[2][1], bfr[3][0], bfr[3][1], ka + SB + boff + 2304);
#pragma unroll
            for (int mt = 0; mt < 4; mt++) {
                uint32_t av[4];
                LDSM4(av[0], av[1], av[2], av[3], ka + SA + aoff + mt * 2304);
#pragma unroll
                for (int nt = 0; nt < 4; nt++) MMA(acc[mt][nt], av, bfr[nt]);
            }
        }
        const int cn = c + 2;
        if (cn < nch)
            stage_copy(sb + (uint32_t)(cn % NSTAGE) * STAGE_B,
                       pA, pB, m0, ldA, n0, ldB, cn * 64, tid);
        CP_COMMIT();
    }

    // ---------------- epilogue ----------------
    if (MODE == 3 && isQK) {
        // fused exp: P~ = exp(min(s,10)) (0 above diagonal) + per-row partial sums
        __half* P = gP16 + (size_t)bb * SSZ;
        float* rowsum = (float*)smem;
        __syncthreads();                 // mainloop finished; reuse smem
        if (tid < 128) rowsum[tid] = 0.0f;
        __syncthreads();
#pragma unroll
        for (int mt = 0; mt < 4; mt++) {
            const int r = m0 + wm + mt * 16 + g;
            float s0 = 0.0f, s1 = 0.0f;
#pragma unroll
            for (int nt = 0; nt < 4; nt++) {
                const float* a = acc[mt][nt];
                const int cc = n0 + wn + nt * 8 + 2 * t;
                const float e0 = (cc     <= r) ? __expf(fminf(a[0], 10.0f)) : 0.0f;
                const float e1 = (cc + 1 <= r) ? __expf(fminf(a[1], 10.0f)) : 0.0f;
                const float e2 = (cc     <= r + 8) ? __expf(fminf(a[2], 10.0f)) : 0.0f;
                const float e3 = (cc + 1 <= r + 8) ? __expf(fminf(a[3], 10.0f)) : 0.0f;
                store_single(P + (size_t)r * SEQ + cc, e0, e1);
                store_single(P + (size_t)(r + 8) * SEQ + cc, e2, e3);
                s0 += e0 + e1;
                s1 += e2 + e3;
            }
            s0 += __shfl_xor_sync(~0u, s0, 1); s0 += __shfl_xor_sync(~0u, s0, 2);
            s1 += __shfl_xor_sync(~0u, s1, 1); s1 += __shfl_xor_sync(~0u, s1, 2);
            if (t == 0) {
                atomicAdd(&rowsum[wm + mt * 16 + g], s0);
                atomicAdd(&rowsum[wm + mt * 16 + g + 8], s1);
            }
        }
        __syncthreads();
        if (tid < 128)
            gPart[(((size_t)bb * 16 + (m0 >> 7)) * 16 + (n0 >> 7)) * 128 + tid] = rowsum[tid];
        return;
    }

    float* invb = (float*)smem;
    if (MODE == 2) {
        // inline row-sum inversion (jt ascending: deterministic)
        const int by = m0 >> 7;
        __syncthreads();                 // mainloop finished; reuse smem
        if (tid < 128) {
            float s = 0.0f;
            const size_t basep = (((size_t)bb * 16 + by) * 16) * 128 + tid;
            for (int jt = 0; jt <= by; jt++)
                s += gPart[basep + (size_t)jt * 128];
            invb[tid] = 1.0f / s;
        }
        __syncthreads();
    }

#pragma unroll
    for (int mt = 0; mt < 4; mt++) {
        const int r = m0 + wm + mt * 16 + g;
        float i0 = 1.0f, i1 = 1.0f;
        if (MODE == 2) {
            i0 = invb[wm + mt * 16 + g];
            i1 = invb[wm + mt * 16 + g + 8];
        }
#pragma unroll
        for (int nt = 0; nt < 4; nt++) {
            const float* a = acc[mt][nt];
            const int cc = n0 + wn + nt * 8 + 2 * t;
            if (MODE == 0) {
                if (blockIdx.z == 0) {   // Q pre-scaled by 1/32 (exact power of 2)
                    store_single(gQ16 + (size_t)r * DIM + cc,
                                 a[0] * 0.03125f, a[1] * 0.03125f);
                    store_single(gQ16 + (size_t)(r + 8) * DIM + cc,
                                 a[2] * 0.03125f, a[3] * 0.03125f);
                } else {
                    store_single(gK16 + (size_t)r * DIM + cc, a[0], a[1]);
                    store_single(gK16 + (size_t)(r + 8) * DIM + cc, a[2], a[3]);
                }
            } else if (MODE == 3) {      // V^T store
                const int b = cc >> 11, s = cc & (SEQ - 1);
                const size_t base = (size_t)b * SD;
                store_single(gVt16 + base + (size_t)r * SEQ + s, a[0], a[1]);
                store_single(gVt16 + base + (size_t)(r + 8) * SEQ + s, a[2], a[3]);
            } else {                     // MODE 2: O = (P~ . V) * inv_rowsum
                float* O = out + (size_t)bb * SD;
                float2 v0, v1;
                v0.x = a[0] * i0; v0.y = a[1] * i0;
                v1.x = a[2] * i1; v1.y = a[3] * i1;
                *(float2*)(O + (size_t)r * DIM + cc)       = v0;
                *(float2*)(O + (size_t)(r + 8) * DIM + cc) = v1;
            }
        }
    }
}

// ====== fp32 -> fp16 convert, vectorized: 8 floats per thread ======
// 5632 CTAs x 256 threads x 8 floats = 11,534,336 = XSZ + 3*WSZ exactly.
__global__ __launch_bounds__(256) void conv_kernel(const float* __restrict__ x,
                                                   const float* __restrict__ wq,
                                                   const float* __restrict__ wk,
                                                   const float* __restrict__ wv)
{
    const int i = blockIdx.x * 256 + threadIdx.x;   // 8-float chunk id
    const float4* sp;
    uint4* dp;
    int off;
    if (i < 1048576) {                   // x: XSZ/8 = 1048576 chunks
        sp = (const float4*)x;
        dp = (uint4*)gX16;
        off = i;
    } else {                             // W: 3 x 131072 chunks
        const int r = i - 1048576;
        const int w = r >> 17;           // WSZ/8 = 131072 = 2^17
        off = r & 131071;
        sp = (const float4*)((w == 0) ? wq : (w == 1) ? wk : wv);
        dp = (uint4*)(gW16 + (size_t)w * WSZ);
    }
    const float4 a = sp[2 * off];
    const float4 b = sp[2 * off + 1];
    __half2 h0 = __halves2half2(__float2half(a.x), __float2half(a.y));
    __half2 h1 = __halves2half2(__float2half(a.z), __float2half(a.w));
    __half2 h2 = __halves2half2(__float2half(b.x), __float2half(b.y));
    __half2 h3 = __halves2half2(__float2half(b.z), __float2half(b.w));
    uint4 u;
    u.x = *reinterpret_cast<uint32_t*>(&h0);
    u.y = *reinterpret_cast<uint32_t*>(&h1);
    u.z = *reinterpret_cast<uint32_t*>(&h2);
    u.w = *reinterpret_cast<uint32_t*>(&h3);
    dp[off] = u;
}

// ---------------------------------------------------------------------------
extern "C" void kernel_launch(void* const* d_in, const int* in_sizes, int n_in,
                              void* d_out, int out_size)
{
    (void)in_sizes; (void)n_in; (void)out_size;
    const float* x  = (const float*)d_in[0];
    const float* wq = (const float*)d_in[1];
    const float* wk = (const float*)d_in[2];
    const float* wv = (const float*)d_in[3];
    float* out = (float*)d_out;

    cudaFuncSetAttribute(mma_kernel<0>, cudaFuncAttributeMaxDynamicSharedMemorySize, SMEM_TOTAL);
    cudaFuncSetAttribute(mma_kernel<3>, cudaFuncAttributeMaxDynamicSharedMemorySize, SMEM_TOTAL);
    cudaFuncSetAttribute(mma_kernel<2>, cudaFuncAttributeMaxDynamicSharedMemorySize, SMEM_TOTAL);

    // fp16 converts (x + W, vectorized)
    conv_kernel<<<5632, 256>>>(x, wq, wk, wv);
    // Q (pre-scaled) and K projections
    mma_kernel<0><<<dim3(512, 1, 2), 256, SMEM_TOTAL>>>(nullptr);
    // fused: causal scores + exp + partial sums (544 CTAs, heavy-first) + V^T proj (512 CTAs)
    mma_kernel<3><<<1056, 256, SMEM_TOTAL>>>(nullptr);
    // O = (P~ . V) * inv, inline row-sum inversion (heavy i-tiles first)
    mma_kernel<2><<<dim3(8 * BATCH, 16), 256, SMEM_TOTAL>>>(out);
}